// round 1
// baseline (speedup 1.0000x reference)
#include <cuda_runtime.h>

// ---------------------------------------------------------------------------
// MAHGN: 2-layer hetero GAT. 3 node types (user=200000, article=100000,
// category=500), 8 edge types, D=64, H=4, C=16, L=2.
// ---------------------------------------------------------------------------

#define NU 200000
#define NA 100000
#define NC 500
#define DD 64
#define NH 4

// scratch (allowed: __device__ globals)
__device__ float    g_xu[NU*DD], g_xa[NA*DD], g_xc[NC*DD];   // current features
__device__ float    g_ou[NU*DD], g_oa[NA*DD], g_oc[NC*DD];   // layer output accum
__device__ float    g_hs[NU*DD];                             // hs for current edge type
__device__ float    g_as[NU*NH], g_ad[NU*NH];                // per-node attn logits
__device__ unsigned g_m[NU*NH];                              // segment max (ordered bits)
__device__ float    g_den[NU*NH];                            // segment sum
__device__ float    g_accu[NU*DD], g_acci[NA*DD];            // residual mean accumulators

__device__ __forceinline__ float* xp(int s){ return s==0 ? g_xu : (s==1 ? g_xa : g_xc); }
__device__ __forceinline__ float* op(int s){ return s==0 ? g_ou : (s==1 ? g_oa : g_oc); }

// order-preserving float<->uint mapping for atomicMax on floats
__device__ __forceinline__ unsigned ford(float f){
    unsigned u = __float_as_uint(f);
    return (u & 0x80000000u) ? ~u : (u | 0x80000000u);
}
__device__ __forceinline__ float funord(unsigned u){
    u = (u & 0x80000000u) ? (u ^ 0x80000000u) : ~u;
    return __uint_as_float(u);
}
#define ORD_NEGINF 0x007FFFFFu   // ford(-inf)

// ---------------------------------------------------------------------------
// init: copy inputs into working buffers, seed the residual accumulators
// ---------------------------------------------------------------------------
__global__ void k_copy_init(int sel, const float* __restrict__ src, int n, int acc_sel){
    int i = blockIdx.x * blockDim.x + threadIdx.x;
    if (i >= n) return;
    float v = src[i];
    xp(sel)[i] = v;
    if (acc_sel == 0) g_accu[i] = v;
    else if (acc_sel == 1) g_acci[i] = v;
}

// ---------------------------------------------------------------------------
// init out buffer with summed biases of the edge types targeting this dst
// ---------------------------------------------------------------------------
__global__ void k_init_out(int dst_sel, const float* __restrict__ bias, int l,
                           int t0, int t1, int t2, int t3, int n64){
    int i = blockIdx.x * blockDim.x + threadIdx.x;
    if (i >= n64) return;
    int c = i & 63;
    float b = bias[(l*8 + t0)*64 + c];
    if (t1 >= 0) b += bias[(l*8 + t1)*64 + c];
    if (t2 >= 0) b += bias[(l*8 + t2)*64 + c];
    if (t3 >= 0) b += bias[(l*8 + t3)*64 + c];
    op(dst_sel)[i] = b;
}

// ---------------------------------------------------------------------------
// hs = x_src @ Wsrc (64x64), fused a_s[n,h] = sum_c hs[n,h*16+c]*att[h*16+c]
// block = 256 threads, 32 rows per block
// ---------------------------------------------------------------------------
__global__ void k_gemm_hs(int src_sel, const float* __restrict__ W,
                          const float* __restrict__ att, int N){
    __shared__ float sW[64][65];
    __shared__ float sX[32][65];
    __shared__ float sAtt[64];
    __shared__ float sPart[32][8];
    const float* x = xp(src_sel);
    int tid = threadIdx.x;

    for (int i = tid; i < 4096; i += 256) sW[i >> 6][i & 63] = W[i];
    if (tid < 64) sAtt[tid] = att[tid];

    int row0 = blockIdx.x * 32;
    for (int i = tid; i < 2048; i += 256){
        int r = i >> 6, c = i & 63;
        int gr = row0 + r;
        sX[r][c] = (gr < N) ? x[gr*64 + c] : 0.f;
    }
    __syncthreads();

    int r  = tid >> 3;      // 0..31
    int cg = tid & 7;       // 0..7
    int c0 = cg * 8;
    float acc[8];
#pragma unroll
    for (int j = 0; j < 8; j++) acc[j] = 0.f;
#pragma unroll
    for (int k = 0; k < 64; k++){
        float xv = sX[r][k];
#pragma unroll
        for (int j = 0; j < 8; j++) acc[j] += xv * sW[k][c0 + j];
    }
    float part = 0.f;
#pragma unroll
    for (int j = 0; j < 8; j++) part += acc[j] * sAtt[c0 + j];
    sPart[r][cg] = part;

    int gr = row0 + r;
    if (gr < N){
        float4* o = (float4*)&g_hs[gr*64 + c0];
        o[0] = make_float4(acc[0], acc[1], acc[2], acc[3]);
        o[1] = make_float4(acc[4], acc[5], acc[6], acc[7]);
    }
    __syncthreads();
    if (tid < 128){
        int rr = tid >> 2, h = tid & 3;
        int grr = row0 + rr;
        if (grr < N) g_as[grr*4 + h] = sPart[rr][2*h] + sPart[rr][2*h + 1];
    }
}

// ---------------------------------------------------------------------------
// a_d[n,h] = x_dst[n,:] @ wdatt[:,h], wdatt[k,h] = sum_c Wd[k,h*16+c]*attd[h*16+c]
// also resets g_m / g_den. block = 256 threads, 64 rows per block.
// ---------------------------------------------------------------------------
__global__ void k_ad(int dst_sel, const float* __restrict__ Wd,
                     const float* __restrict__ attd, int N){
    __shared__ float sWd[64][4];
    __shared__ float sX[64][65];
    const float* x = xp(dst_sel);
    int tid = threadIdx.x;

    {   // fold Wd with att_dst: 256 entries
        int k = tid >> 2, h = tid & 3;
        float s = 0.f;
#pragma unroll
        for (int c = 0; c < 16; c++) s += Wd[k*64 + h*16 + c] * attd[h*16 + c];
        sWd[k][h] = s;
    }
    int row0 = blockIdx.x * 64;
    for (int i = tid; i < 4096; i += 256){
        int r = i >> 6, c = i & 63;
        int gr = row0 + r;
        sX[r][c] = (gr < N) ? x[gr*64 + c] : 0.f;
    }
    __syncthreads();

    int r = tid >> 2, h = tid & 3;
    int gr = row0 + r;
    if (gr < N){
        float s = 0.f;
#pragma unroll
        for (int k = 0; k < 64; k++) s += sX[r][k] * sWd[k][h];
        g_ad[gr*4 + h]  = s;
        g_m[gr*4 + h]   = ORD_NEGINF;
        g_den[gr*4 + h] = 0.f;
    }
}

// ---------------------------------------------------------------------------
// edge pass 1: segment max of leaky_relu(a_s[row]+a_d[col], 0.2)
// ---------------------------------------------------------------------------
__global__ void k_pass1(const int* __restrict__ ei, int E){
    int e = blockIdx.x * blockDim.x + threadIdx.x;
    if (e >= E) return;
    int row = ei[e], col = ei[E + e];
    float4 a = *(const float4*)&g_as[row*4];
    float4 b = *(const float4*)&g_ad[col*4];
    float v[4] = {a.x + b.x, a.y + b.y, a.z + b.z, a.w + b.w};
#pragma unroll
    for (int h = 0; h < 4; h++){
        float ev = v[h] > 0.f ? v[h] : 0.2f * v[h];
        atomicMax(&g_m[col*4 + h], ford(ev));
    }
}

// ---------------------------------------------------------------------------
// edge pass 2: segment sum of exp(e - m)
// ---------------------------------------------------------------------------
__global__ void k_pass2(const int* __restrict__ ei, int E){
    int e = blockIdx.x * blockDim.x + threadIdx.x;
    if (e >= E) return;
    int row = ei[e], col = ei[E + e];
    float4 a = *(const float4*)&g_as[row*4];
    float4 b = *(const float4*)&g_ad[col*4];
    float v[4] = {a.x + b.x, a.y + b.y, a.z + b.z, a.w + b.w};
#pragma unroll
    for (int h = 0; h < 4; h++){
        float ev = v[h] > 0.f ? v[h] : 0.2f * v[h];
        float mf = funord(g_m[col*4 + h]);
        atomicAdd(&g_den[col*4 + h], __expf(ev - mf));
    }
}

// ---------------------------------------------------------------------------
// edge pass 3: out[col, h*16+c] += hs[row, h*16+c] * softmax_w  (1 thread per
// (edge, head): 4 float4 gathers + 16 atomicAdds)
// ---------------------------------------------------------------------------
__global__ void k_pass3(const int* __restrict__ ei, int E, int dst_sel){
    long long idx = (long long)blockIdx.x * blockDim.x + threadIdx.x;
    if (idx >= (long long)E * 4) return;
    int e = (int)(idx >> 2), h = (int)(idx & 3);
    int row = ei[e], col = ei[E + e];
    float ev = g_as[row*4 + h] + g_ad[col*4 + h];
    ev = ev > 0.f ? ev : 0.2f * ev;
    float mf = funord(g_m[col*4 + h]);
    float w  = __expf(ev - mf) / (g_den[col*4 + h] + 1e-16f);
    const float4* hv = (const float4*)&g_hs[row*64 + h*16];
    float* ob = op(dst_sel) + col*64 + h*16;
#pragma unroll
    for (int q = 0; q < 4; q++){
        float4 v = hv[q];
        atomicAdd(&ob[q*4 + 0], v.x * w);
        atomicAdd(&ob[q*4 + 1], v.y * w);
        atomicAdd(&ob[q*4 + 2], v.z * w);
        atomicAdd(&ob[q*4 + 3], v.w * w);
    }
}

// ---------------------------------------------------------------------------
// activation: x = leaky_relu(out, 0.01); accumulate residual mean
// ---------------------------------------------------------------------------
__global__ void k_act(int sel, int n64){
    int i = blockIdx.x * blockDim.x + threadIdx.x;
    if (i >= n64) return;
    float v = op(sel)[i];
    v = v > 0.f ? v : 0.01f * v;
    xp(sel)[i] = v;
    if (sel == 0) g_accu[i] += v;
    else if (sel == 1) g_acci[i] += v;
}

// ---------------------------------------------------------------------------
// final: d_out = [user_final (NU*64), item_final (NA*64)] = acc/3
// ---------------------------------------------------------------------------
__global__ void k_final(float* __restrict__ out){
    int i = blockIdx.x * blockDim.x + threadIdx.x;
    const int nu = NU * DD;
    const int tot = nu + NA * DD;
    if (i >= tot) return;
    const float s = 1.f / 3.f;
    out[i] = (i < nu) ? g_accu[i] * s : g_acci[i - nu] * s;
}

// ---------------------------------------------------------------------------
static inline int cdiv(long long a, int b){ return (int)((a + b - 1) / b); }

extern "C" void kernel_launch(void* const* d_in, const int* in_sizes, int n_in,
                              void* d_out, int out_size){
    const float* x_user    = (const float*)d_in[0];
    const float* x_article = (const float*)d_in[1];
    const float* x_cat     = (const float*)d_in[2];
    const float* Wsrc      = (const float*)d_in[3];   // [2,8,64,64]
    const float* Wdst      = (const float*)d_in[4];   // [2,8,64,64]
    const float* att_src   = (const float*)d_in[5];   // [2,8,4,16]
    const float* att_dst   = (const float*)d_in[6];   // [2,8,4,16]
    const float* bias      = (const float*)d_in[7];   // [2,8,64]
    float* out = (float*)d_out;

    static const int SRC[8]  = {0, 1, 0, 0, 1, 2, 0, 2};
    static const int DSTT[8] = {1, 0, 0, 0, 2, 1, 2, 0};
    static const int NN[3]   = {NU, NA, NC};

    // init working features + residual accumulators
    k_copy_init<<<cdiv((long long)NU*DD, 256), 256>>>(0, x_user,    NU*DD, 0);
    k_copy_init<<<cdiv((long long)NA*DD, 256), 256>>>(1, x_article, NA*DD, 1);
    k_copy_init<<<cdiv((long long)NC*DD, 256), 256>>>(2, x_cat,     NC*DD, -1);

    for (int l = 0; l < 2; l++){
        // bias pre-sum per destination type
        k_init_out<<<cdiv((long long)NU*DD, 256), 256>>>(0, bias, l, 1, 2, 3, 7, NU*DD);
        k_init_out<<<cdiv((long long)NA*DD, 256), 256>>>(1, bias, l, 0, 5, -1, -1, NA*DD);
        k_init_out<<<cdiv((long long)NC*DD, 256), 256>>>(2, bias, l, 4, 6, -1, -1, NC*DD);

        for (int t = 0; t < 8; t++){
            const int*   ei = (const int*)d_in[8 + t];
            const int    E  = in_sizes[8 + t] / 2;
            const int    ns = NN[SRC[t]], nd = NN[DSTT[t]];
            const float* W  = Wsrc    + (size_t)(l*8 + t) * 64 * 64;
            const float* Wd = Wdst    + (size_t)(l*8 + t) * 64 * 64;
            const float* as = att_src + (size_t)(l*8 + t) * 64;
            const float* ad = att_dst + (size_t)(l*8 + t) * 64;

            k_gemm_hs<<<cdiv(ns, 32), 256>>>(SRC[t], W, as, ns);
            k_ad    <<<cdiv(nd, 64), 256>>>(DSTT[t], Wd, ad, nd);
            k_pass1 <<<cdiv(E, 256), 256>>>(ei, E);
            k_pass2 <<<cdiv(E, 256), 256>>>(ei, E);
            k_pass3 <<<cdiv((long long)E*4, 256), 256>>>(ei, E, DSTT[t]);
        }

        k_act<<<cdiv((long long)NU*DD, 256), 256>>>(0, NU*DD);
        k_act<<<cdiv((long long)NA*DD, 256), 256>>>(1, NA*DD);
        k_act<<<cdiv((long long)NC*DD, 256), 256>>>(2, NC*DD);
    }

    k_final<<<cdiv((long long)(NU + NA) * DD, 256), 256>>>(out);
}

// round 3
// speedup vs baseline: 1.4417x; 1.4417x over previous
#include <cuda_runtime.h>

// ---------------------------------------------------------------------------
// MAHGN: 2-layer hetero GAT. 3 node types (user=200000, article=100000,
// category=500), 8 edge types, D=64, H=4, C=16, L=2.
//
// R3: R2 (fused softmax, red.v4 scatters, single edge pass) with two fixes:
//  - denominator quad-shuffle operand order {ex, ex^1, ex^2, ex^3}
//  - no early-return before __shfl_xor_sync (tail-warp UB)
// ---------------------------------------------------------------------------

#define NU 200000
#define NA 100000
#define NC 500
#define DD 64
#define NH 4

// scratch (allowed: __device__ globals)
__device__ float g_xu[NU*DD], g_xa[NA*DD], g_xc[NC*DD];   // current features
__device__ float g_ou[NU*DD], g_oa[NA*DD], g_oc[NC*DD];   // layer output accum
__device__ float g_hs[NU*DD];                             // hs for current edge type
__device__ float g_tmp[NU*DD];                            // unnormalized message accum
__device__ float g_as[NU*NH], g_ad[NU*NH];                // per-node attn logits
__device__ float g_den[NU*NH];                            // softmax denominator
__device__ float g_accu[NU*DD], g_acci[NA*DD];            // residual mean accumulators

__device__ __forceinline__ float* xp(int s){ return s==0 ? g_xu : (s==1 ? g_xa : g_xc); }
__device__ __forceinline__ float* op(int s){ return s==0 ? g_ou : (s==1 ? g_oa : g_oc); }

__device__ __forceinline__ void red_v4(float* p, float a, float b, float c, float d){
    asm volatile("red.global.add.v4.f32 [%0], {%1,%2,%3,%4};"
                 :: "l"(p), "f"(a), "f"(b), "f"(c), "f"(d) : "memory");
}

// ---------------------------------------------------------------------------
// init: copy inputs into working buffers, seed the residual accumulators
// ---------------------------------------------------------------------------
__global__ void k_copy_init(int sel, const float* __restrict__ src, int n, int acc_sel){
    int i = blockIdx.x * blockDim.x + threadIdx.x;
    if (i >= n) return;
    float v = src[i];
    xp(sel)[i] = v;
    if (acc_sel == 0) g_accu[i] = v;
    else if (acc_sel == 1) g_acci[i] = v;
}

// ---------------------------------------------------------------------------
// init out buffer with summed biases of the edge types targeting this dst
// ---------------------------------------------------------------------------
__global__ void k_init_out(int dst_sel, const float* __restrict__ bias, int l,
                           int t0, int t1, int t2, int t3, int n64){
    int i = blockIdx.x * blockDim.x + threadIdx.x;
    if (i >= n64) return;
    int c = i & 63;
    float b = bias[(l*8 + t0)*64 + c];
    if (t1 >= 0) b += bias[(l*8 + t1)*64 + c];
    if (t2 >= 0) b += bias[(l*8 + t2)*64 + c];
    if (t3 >= 0) b += bias[(l*8 + t3)*64 + c];
    op(dst_sel)[i] = b;
}

// ---------------------------------------------------------------------------
// hs = x_src @ Wsrc (64x64), fused a_s[n,h] = sum_c hs[n,h*16+c]*att[h*16+c]
// block = 256 threads, 32 rows per block
// ---------------------------------------------------------------------------
__global__ void k_gemm_hs(int src_sel, const float* __restrict__ W,
                          const float* __restrict__ att, int N){
    __shared__ float sW[64][65];
    __shared__ float sX[32][65];
    __shared__ float sAtt[64];
    __shared__ float sPart[32][8];
    const float* x = xp(src_sel);
    int tid = threadIdx.x;

    for (int i = tid; i < 4096; i += 256) sW[i >> 6][i & 63] = W[i];
    if (tid < 64) sAtt[tid] = att[tid];

    int row0 = blockIdx.x * 32;
    for (int i = tid; i < 2048; i += 256){
        int r = i >> 6, c = i & 63;
        int gr = row0 + r;
        sX[r][c] = (gr < N) ? x[gr*64 + c] : 0.f;
    }
    __syncthreads();

    int r  = tid >> 3;      // 0..31
    int cg = tid & 7;       // 0..7
    int c0 = cg * 8;
    float acc[8];
#pragma unroll
    for (int j = 0; j < 8; j++) acc[j] = 0.f;
#pragma unroll
    for (int k = 0; k < 64; k++){
        float xv = sX[r][k];
#pragma unroll
        for (int j = 0; j < 8; j++) acc[j] += xv * sW[k][c0 + j];
    }
    float part = 0.f;
#pragma unroll
    for (int j = 0; j < 8; j++) part += acc[j] * sAtt[c0 + j];
    sPart[r][cg] = part;

    int gr = row0 + r;
    if (gr < N){
        float4* o = (float4*)&g_hs[gr*64 + c0];
        o[0] = make_float4(acc[0], acc[1], acc[2], acc[3]);
        o[1] = make_float4(acc[4], acc[5], acc[6], acc[7]);
    }
    __syncthreads();
    if (tid < 128){
        int rr = tid >> 2, h = tid & 3;
        int grr = row0 + rr;
        if (grr < N) g_as[grr*4 + h] = sPart[rr][2*h] + sPart[rr][2*h + 1];
    }
}

// ---------------------------------------------------------------------------
// a_d[n,h] = x_dst[n,:] @ wdatt[:,h], wdatt[k,h] = sum_c Wd[k,h*16+c]*attd[h*16+c]
// Also zeros g_den and g_tmp for this dst set.
// block = 256 threads, 64 rows per block.
// ---------------------------------------------------------------------------
__global__ void k_ad(int dst_sel, const float* __restrict__ Wd,
                     const float* __restrict__ attd, int N){
    __shared__ float sWd[64][4];
    __shared__ float sX[64][65];
    const float* x = xp(dst_sel);
    int tid = threadIdx.x;

    {   // fold Wd with att_dst: 256 entries
        int k = tid >> 2, h = tid & 3;
        float s = 0.f;
#pragma unroll
        for (int c = 0; c < 16; c++) s += Wd[k*64 + h*16 + c] * attd[h*16 + c];
        sWd[k][h] = s;
    }
    int row0 = blockIdx.x * 64;
    for (int i = tid; i < 4096; i += 256){
        int r = i >> 6, c = i & 63;
        int gr = row0 + r;
        sX[r][c] = (gr < N) ? x[gr*64 + c] : 0.f;
    }
    __syncthreads();

    int r = tid >> 2, h = tid & 3;
    int gr = row0 + r;
    if (gr < N){
        float s = 0.f;
#pragma unroll
        for (int k = 0; k < 64; k++) s += sX[r][k] * sWd[k][h];
        g_ad[gr*4 + h]  = s;
        g_den[gr*4 + h] = 0.f;
        // zero the unnormalized accumulator (16 floats per (r,h) thread)
        float4 z = make_float4(0.f, 0.f, 0.f, 0.f);
        float4* tz = (float4*)&g_tmp[gr*64 + h*16];
        tz[0] = z; tz[1] = z; tz[2] = z; tz[3] = z;
    }
}

// ---------------------------------------------------------------------------
// single edge pass: one thread per (edge, head).
//   ex = exp(leaky_relu(a_s[row]+a_d[col], 0.2))
//   g_tmp[col, h*16..] += ex * hs[row, h*16..]   (4x red.v4)
//   g_den[col*4..]     += {ex_h0..h3}            (1x red.v4, quad lane h==0)
// NOTE: no early return — all threads reach the quad shuffles (full mask is
// legal); invalid quads (uniform per quad) skip the global reductions.
// ---------------------------------------------------------------------------
__global__ void k_edge(const int* __restrict__ ei, int E){
    long long idx = (long long)blockIdx.x * blockDim.x + threadIdx.x;
    bool valid = idx < (long long)E * 4;
    long long cidx = valid ? idx : 0;
    int e = (int)(cidx >> 2), h = (int)(cidx & 3);
    int row = __ldg(&ei[e]), col = __ldg(&ei[E + e]);

    float ev = g_as[row*4 + h] + g_ad[col*4 + h];
    ev = ev > 0.f ? ev : 0.2f * ev;
    float ex = __expf(ev);

    // quad-aggregated denominator reduction (lanes e*4+h, h=0..3 share an edge)
    float ex1 = __shfl_xor_sync(0xffffffffu, ex, 1);  // h^1
    float ex2 = __shfl_xor_sync(0xffffffffu, ex, 2);  // h^2
    float ex3 = __shfl_xor_sync(0xffffffffu, ex, 3);  // h^3
    if (valid && h == 0)
        red_v4(&g_den[col*4], ex, ex1, ex2, ex3);     // h0,h1,h2,h3

    if (valid){
        const float4* hv = (const float4*)&g_hs[row*64 + h*16];
        float* tb = &g_tmp[col*64 + h*16];
#pragma unroll
        for (int q = 0; q < 4; q++){
            float4 v = hv[q];
            red_v4(tb + q*4, v.x * ex, v.y * ex, v.z * ex, v.w * ex);
        }
    }
}

// ---------------------------------------------------------------------------
// normalize: out[n, c] += tmp[n, c] / (den[n, h(c)] + 1e-16)
// ---------------------------------------------------------------------------
__global__ void k_norm(int dst_sel, int n64){
    int i = blockIdx.x * blockDim.x + threadIdx.x;
    if (i >= n64) return;
    int n = i >> 6, c = i & 63, h = c >> 4;
    float d = g_den[n*4 + h] + 1e-16f;
    op(dst_sel)[i] += g_tmp[i] / d;
}

// ---------------------------------------------------------------------------
// activation: x = leaky_relu(out, 0.01); accumulate residual mean
// ---------------------------------------------------------------------------
__global__ void k_act(int sel, int n64){
    int i = blockIdx.x * blockDim.x + threadIdx.x;
    if (i >= n64) return;
    float v = op(sel)[i];
    v = v > 0.f ? v : 0.01f * v;
    xp(sel)[i] = v;
    if (sel == 0) g_accu[i] += v;
    else if (sel == 1) g_acci[i] += v;
}

// ---------------------------------------------------------------------------
// final: d_out = [user_final (NU*64), item_final (NA*64)] = acc/3
// ---------------------------------------------------------------------------
__global__ void k_final(float* __restrict__ out){
    int i = blockIdx.x * blockDim.x + threadIdx.x;
    const int nu = NU * DD;
    const int tot = nu + NA * DD;
    if (i >= tot) return;
    const float s = 1.f / 3.f;
    out[i] = (i < nu) ? g_accu[i] * s : g_acci[i - nu] * s;
}

// ---------------------------------------------------------------------------
static inline int cdiv(long long a, int b){ return (int)((a + b - 1) / b); }

extern "C" void kernel_launch(void* const* d_in, const int* in_sizes, int n_in,
                              void* d_out, int out_size){
    const float* x_user    = (const float*)d_in[0];
    const float* x_article = (const float*)d_in[1];
    const float* x_cat     = (const float*)d_in[2];
    const float* Wsrc      = (const float*)d_in[3];   // [2,8,64,64]
    const float* Wdst      = (const float*)d_in[4];   // [2,8,64,64]
    const float* att_src   = (const float*)d_in[5];   // [2,8,4,16]
    const float* att_dst   = (const float*)d_in[6];   // [2,8,4,16]
    const float* bias      = (const float*)d_in[7];   // [2,8,64]
    float* out = (float*)d_out;

    static const int SRC[8]  = {0, 1, 0, 0, 1, 2, 0, 2};
    static const int DSTT[8] = {1, 0, 0, 0, 2, 1, 2, 0};
    static const int NN[3]   = {NU, NA, NC};

    // init working features + residual accumulators
    k_copy_init<<<cdiv((long long)NU*DD, 256), 256>>>(0, x_user,    NU*DD, 0);
    k_copy_init<<<cdiv((long long)NA*DD, 256), 256>>>(1, x_article, NA*DD, 1);
    k_copy_init<<<cdiv((long long)NC*DD, 256), 256>>>(2, x_cat,     NC*DD, -1);

    for (int l = 0; l < 2; l++){
        // bias pre-sum per destination type
        k_init_out<<<cdiv((long long)NU*DD, 256), 256>>>(0, bias, l, 1, 2, 3, 7, NU*DD);
        k_init_out<<<cdiv((long long)NA*DD, 256), 256>>>(1, bias, l, 0, 5, -1, -1, NA*DD);
        k_init_out<<<cdiv((long long)NC*DD, 256), 256>>>(2, bias, l, 4, 6, -1, -1, NC*DD);

        for (int t = 0; t < 8; t++){
            const int*   ei = (const int*)d_in[8 + t];
            const int    E  = in_sizes[8 + t] / 2;
            const int    ns = NN[SRC[t]], nd = NN[DSTT[t]];
            const float* W  = Wsrc    + (size_t)(l*8 + t) * 64 * 64;
            const float* Wd = Wdst    + (size_t)(l*8 + t) * 64 * 64;
            const float* as = att_src + (size_t)(l*8 + t) * 64;
            const float* ad = att_dst + (size_t)(l*8 + t) * 64;

            k_gemm_hs<<<cdiv(ns, 32), 256>>>(SRC[t], W, as, ns);
            k_ad    <<<cdiv(nd, 64), 256>>>(DSTT[t], Wd, ad, nd);
            k_edge  <<<cdiv((long long)E*4, 256), 256>>>(ei, E);
            k_norm  <<<cdiv((long long)nd*DD, 256), 256>>>(DSTT[t], nd*DD);
        }

        k_act<<<cdiv((long long)NU*DD, 256), 256>>>(0, NU*DD);
        k_act<<<cdiv((long long)NA*DD, 256), 256>>>(1, NA*DD);
        k_act<<<cdiv((long long)NC*DD, 256), 256>>>(2, NC*DD);
    }

    k_final<<<cdiv((long long)(NU + NA) * DD, 256), 256>>>(out);
}